// round 1
// baseline (speedup 1.0000x reference)
#include <cuda_runtime.h>
#include <cuda_bf16.h>
#include <math.h>

// Problem constants
#define BB 8
#define SS 2048
#define DD 1024
#define HH 128
#define MTOT (BB*SS)   // 16384

// Scratch (allocation-free rule: __device__ globals)
__device__ float g_qt[(size_t)BB*HH*SS];  // [b][h][s]  (transposed)
__device__ float g_kt[(size_t)BB*HH*SS];  // [b][h][s]  (transposed)
__device__ float g_v [(size_t)BB*SS*HH];  // [b][s][h]

// ---------------------------------------------------------------------------
// Kernel A: QKV projection GEMM.  C[M=16384, N=128] = x @ W + b
// blockIdx.y selects {q,k,v}. 128x128 block tile, BK=16, 8x8 per thread.
// q,k written transposed [b][h][s]; v written natural [b][s][h].
// ---------------------------------------------------------------------------
__global__ __launch_bounds__(256, 2)
void qkv_kernel(const float* __restrict__ x,
                const float* __restrict__ Wq, const float* __restrict__ bq,
                const float* __restrict__ Wk, const float* __restrict__ bk,
                const float* __restrict__ Wv, const float* __restrict__ bv)
{
    const int which = blockIdx.y;
    const float* W    = (which == 0) ? Wq : (which == 1) ? Wk : Wv;
    const float* bias = (which == 0) ? bq : (which == 1) ? bk : bv;
    const int m0 = blockIdx.x * 128;

    __shared__ float As[16][132];   // [k][m], padded
    __shared__ float Bs[16][128];   // [k][n]

    const int tid = threadIdx.x;
    const int tx = tid & 15;        // n dim
    const int ty = tid >> 4;        // m dim

    float acc[8][8];
#pragma unroll
    for (int i = 0; i < 8; i++)
#pragma unroll
        for (int j = 0; j < 8; j++) acc[i][j] = 0.f;

    for (int k0 = 0; k0 < DD; k0 += 16) {
        // Load A tile (128 rows x 16 k), transpose into As[k][m]
#pragma unroll
        for (int it = 0; it < 2; it++) {
            int idx = tid + it * 256;          // 0..511
            int row = idx >> 2;                // 0..127
            int kq  = idx & 3;                 // float4 group in k
            float4 a = *(const float4*)&x[(size_t)(m0 + row) * DD + k0 + kq * 4];
            As[kq * 4 + 0][row] = a.x;
            As[kq * 4 + 1][row] = a.y;
            As[kq * 4 + 2][row] = a.z;
            As[kq * 4 + 3][row] = a.w;
        }
        // Load B tile (16 k x 128 n)
#pragma unroll
        for (int it = 0; it < 2; it++) {
            int idx = tid + it * 256;          // 0..511
            int kr  = idx >> 5;                // 0..15
            int c4  = idx & 31;                // 0..31
            *(float4*)&Bs[kr][c4 * 4] =
                *(const float4*)&W[(size_t)(k0 + kr) * HH + c4 * 4];
        }
        __syncthreads();

#pragma unroll
        for (int kk = 0; kk < 16; kk++) {
            float ra[8], rb[8];
            *(float4*)&ra[0] = *(const float4*)&As[kk][ty * 8];
            *(float4*)&ra[4] = *(const float4*)&As[kk][ty * 8 + 4];
            *(float4*)&rb[0] = *(const float4*)&Bs[kk][tx * 8];
            *(float4*)&rb[4] = *(const float4*)&Bs[kk][tx * 8 + 4];
#pragma unroll
            for (int i = 0; i < 8; i++)
#pragma unroll
                for (int j = 0; j < 8; j++)
                    acc[i][j] += ra[i] * rb[j];
        }
        __syncthreads();
    }

    // Epilogue
    if (which == 2) {
        // v natural: [b][s][h] == [m][n]
#pragma unroll
        for (int i = 0; i < 8; i++) {
            size_t m = (size_t)(m0 + ty * 8 + i);
            float4 o0, o1;
            o0.x = acc[i][0] + bias[tx * 8 + 0];
            o0.y = acc[i][1] + bias[tx * 8 + 1];
            o0.z = acc[i][2] + bias[tx * 8 + 2];
            o0.w = acc[i][3] + bias[tx * 8 + 3];
            o1.x = acc[i][4] + bias[tx * 8 + 4];
            o1.y = acc[i][5] + bias[tx * 8 + 5];
            o1.z = acc[i][6] + bias[tx * 8 + 6];
            o1.w = acc[i][7] + bias[tx * 8 + 7];
            *(float4*)&g_v[m * HH + tx * 8]     = o0;
            *(float4*)&g_v[m * HH + tx * 8 + 4] = o1;
        }
    } else {
        // q/k transposed: [b][h][s]
        float* dst = (which == 0) ? g_qt : g_kt;
        int b  = m0 / SS;
        int s0 = (m0 % SS) + ty * 8;
#pragma unroll
        for (int j = 0; j < 8; j++) {
            int n = tx * 8 + j;
            float bn = bias[n];
            float4 v0, v1;
            v0.x = acc[0][j] + bn; v0.y = acc[1][j] + bn;
            v0.z = acc[2][j] + bn; v0.w = acc[3][j] + bn;
            v1.x = acc[4][j] + bn; v1.y = acc[5][j] + bn;
            v1.z = acc[6][j] + bn; v1.w = acc[7][j] + bn;
            size_t base = ((size_t)b * HH + n) * SS + s0;
            *(float4*)&dst[base]     = v0;
            *(float4*)&dst[base + 4] = v1;
        }
    }
}

// ---------------------------------------------------------------------------
// Kernel B: flash attention, causal, fp32.
// One block = 64 query rows of one batch. Online softmax over 64-key tiles.
// ---------------------------------------------------------------------------
#define TQ 64
#define TK 64
#define SSTR 68   // padded S-tile stride (16B-aligned, conflict-light)

__global__ __launch_bounds__(256, 1)
void attn_kernel(float* __restrict__ out)
{
    const int b  = blockIdx.y;
    const int qt = (int)gridDim.x - 1 - (int)blockIdx.x;  // heavy blocks first
    const int q0 = qt * TQ;

    extern __shared__ float sm[];
    float* Qt   = sm;                 // [HH][TQ]
    float* Kt   = Qt + HH * TQ;       // [HH][TK]
    float* Vs   = Kt + HH * TK;       // [TK][HH]
    float* Ssm  = Vs + TK * HH;       // [TQ][SSTR]
    float* rowm = Ssm + TQ * SSTR;    // [TQ]
    float* rowl = rowm + TQ;          // [TQ]
    float* rowa = rowl + TQ;          // [TQ]

    const int tid = threadIdx.x;
    const int tx = tid & 15;
    const int ty = tid >> 4;

    const float* qsrc = g_qt + (size_t)b * HH * SS;
    const float* ksrc = g_kt + (size_t)b * HH * SS;
    const float* vsrc = g_v  + (size_t)b * SS * HH;

    // Load Q tile transposed: Qt[h][r]
#pragma unroll
    for (int it = 0; it < 8; it++) {
        int idx = tid + it * 256;   // 0..2047 float4 slots
        int h  = idx >> 4;          // 0..127
        int r4 = idx & 15;          // 0..15
        *(float4*)&Qt[h * TQ + r4 * 4] =
            *(const float4*)&qsrc[(size_t)h * SS + q0 + r4 * 4];
    }
    if (tid < TQ) { rowm[tid] = -1e30f; rowl[tid] = 0.f; }

    float acc[4][8];
#pragma unroll
    for (int i = 0; i < 4; i++)
#pragma unroll
        for (int j = 0; j < 8; j++) acc[i][j] = 0.f;

    for (int kt = 0; kt <= qt; kt++) {
        const int k0 = kt * TK;
        __syncthreads();   // Kt/Vs free to overwrite (also covers Q load + init)

        // Load K tile transposed: Kt[h][r]
#pragma unroll
        for (int it = 0; it < 8; it++) {
            int idx = tid + it * 256;
            int h  = idx >> 4;
            int r4 = idx & 15;
            *(float4*)&Kt[h * TK + r4 * 4] =
                *(const float4*)&ksrc[(size_t)h * SS + k0 + r4 * 4];
        }
        // Load V tile natural: Vs[r][h]
#pragma unroll
        for (int it = 0; it < 8; it++) {
            int idx = tid + it * 256;
            int r  = idx >> 5;          // 0..63
            int c4 = idx & 31;          // 0..31
            *(float4*)&Vs[r * HH + c4 * 4] =
                *(const float4*)&vsrc[(size_t)(k0 + r) * HH + c4 * 4];
        }
        __syncthreads();

        // ---- S = (Q K^T) * 32, 4x4 microtile per thread ----
        float s4[4][4];
#pragma unroll
        for (int i = 0; i < 4; i++)
#pragma unroll
            for (int j = 0; j < 4; j++) s4[i][j] = 0.f;

#pragma unroll 4
        for (int h = 0; h < HH; h++) {
            float4 qv = *(const float4*)&Qt[h * TQ + ty * 4];
            float4 kv = *(const float4*)&Kt[h * TK + tx * 4];
            float qa[4] = {qv.x, qv.y, qv.z, qv.w};
            float ka[4] = {kv.x, kv.y, kv.z, kv.w};
#pragma unroll
            for (int i = 0; i < 4; i++)
#pragma unroll
                for (int j = 0; j < 4; j++)
                    s4[i][j] += qa[i] * ka[j];
        }

        const int qi0 = q0 + ty * 4;
        const int kj0 = k0 + tx * 4;
#pragma unroll
        for (int i = 0; i < 4; i++) {
            float4 sv;
            float v0 = s4[i][0] * 32.f;
            float v1 = s4[i][1] * 32.f;
            float v2 = s4[i][2] * 32.f;
            float v3 = s4[i][3] * 32.f;
            int qi = qi0 + i;
            sv.x = (kj0 + 0 > qi) ? -1e30f : v0;
            sv.y = (kj0 + 1 > qi) ? -1e30f : v1;
            sv.z = (kj0 + 2 > qi) ? -1e30f : v2;
            sv.w = (kj0 + 3 > qi) ? -1e30f : v3;
            *(float4*)&Ssm[(ty * 4 + i) * SSTR + tx * 4] = sv;
        }
        __syncthreads();

        // ---- online softmax: 4 threads per row ----
        {
            int row = tid >> 2, sub = tid & 3;
            float mold = rowm[row];
            float mx = mold;
            float* srow = &Ssm[row * SSTR + sub * 16];
#pragma unroll
            for (int c = 0; c < 16; c++) mx = fmaxf(mx, srow[c]);
            mx = fmaxf(mx, __shfl_xor_sync(0xffffffffu, mx, 1));
            mx = fmaxf(mx, __shfl_xor_sync(0xffffffffu, mx, 2));
            float lsum = 0.f;
#pragma unroll
            for (int c = 0; c < 16; c++) {
                float p = __expf(srow[c] - mx);
                srow[c] = p;
                lsum += p;
            }
            lsum += __shfl_xor_sync(0xffffffffu, lsum, 1);
            lsum += __shfl_xor_sync(0xffffffffu, lsum, 2);
            if (sub == 0) {
                rowa[row] = __expf(mold - mx);
                rowm[row] = mx;
                rowl[row] = rowl[row] * rowa[row] + lsum;
            }
        }
        __syncthreads();

        // ---- acc = acc*alpha + P @ V ----
        float al[4];
#pragma unroll
        for (int i = 0; i < 4; i++) al[i] = rowa[ty * 4 + i];
#pragma unroll
        for (int i = 0; i < 4; i++)
#pragma unroll
            for (int j = 0; j < 8; j++) acc[i][j] *= al[i];

#pragma unroll 2
        for (int k = 0; k < TK; k++) {
            float pr[4];
#pragma unroll
            for (int i = 0; i < 4; i++) pr[i] = Ssm[(ty * 4 + i) * SSTR + k];
            float4 v0 = *(const float4*)&Vs[k * HH + tx * 4];
            float4 v1 = *(const float4*)&Vs[k * HH + 64 + tx * 4];
            float va[8] = {v0.x, v0.y, v0.z, v0.w, v1.x, v1.y, v1.z, v1.w};
#pragma unroll
            for (int i = 0; i < 4; i++)
#pragma unroll
                for (int j = 0; j < 8; j++)
                    acc[i][j] += pr[i] * va[j];
        }
    }

    // ---- epilogue: divide by row sum, write out [b][s][h] ----
    float inv[4];
#pragma unroll
    for (int i = 0; i < 4; i++) inv[i] = 1.f / rowl[ty * 4 + i];
    float* obase = out + ((size_t)b * SS + q0) * HH;
#pragma unroll
    for (int i = 0; i < 4; i++) {
        float4 o0, o1;
        o0.x = acc[i][0] * inv[i]; o0.y = acc[i][1] * inv[i];
        o0.z = acc[i][2] * inv[i]; o0.w = acc[i][3] * inv[i];
        o1.x = acc[i][4] * inv[i]; o1.y = acc[i][5] * inv[i];
        o1.z = acc[i][6] * inv[i]; o1.w = acc[i][7] * inv[i];
        *(float4*)&obase[(size_t)(ty * 4 + i) * HH + tx * 4]      = o0;
        *(float4*)&obase[(size_t)(ty * 4 + i) * HH + 64 + tx * 4] = o1;
    }
}

// ---------------------------------------------------------------------------
extern "C" void kernel_launch(void* const* d_in, const int* in_sizes, int n_in,
                              void* d_out, int out_size)
{
    const float* x  = (const float*)d_in[0];
    const float* Wq = (const float*)d_in[1];
    const float* bq = (const float*)d_in[2];
    const float* Wk = (const float*)d_in[3];
    const float* bk = (const float*)d_in[4];
    const float* Wv = (const float*)d_in[5];
    const float* bv = (const float*)d_in[6];
    float* out = (float*)d_out;

    // Attention kernel needs >48KB dynamic smem
    const int smem_bytes = (HH * TQ + HH * TK + TK * HH + TQ * SSTR + 3 * TQ) * sizeof(float);
    cudaFuncSetAttribute(attn_kernel, cudaFuncAttributeMaxDynamicSharedMemorySize, smem_bytes);

    qkv_kernel<<<dim3(MTOT / 128, 3), 256>>>(x, Wq, bq, Wk, bk, Wv, bv);
    attn_kernel<<<dim3(SS / TQ, BB), 256, smem_bytes>>>(out);
}

// round 4
// speedup vs baseline: 1.3753x; 1.3753x over previous
#include <cuda_runtime.h>
#include <cuda_bf16.h>
#include <math.h>
#include <cstdint>

// Problem constants
#define BB 8
#define SS 2048
#define DD 1024
#define HH 128
#define MTOT (BB*SS)   // 16384

// Scratch (allocation-free rule: __device__ globals)
__device__ float g_qt[(size_t)BB*HH*SS];  // [b][h][s]  (transposed)
__device__ float g_kt[(size_t)BB*HH*SS];  // [b][h][s]  (transposed)
__device__ float g_v [(size_t)BB*SS*HH];  // [b][s][h]

__device__ __nv_bfloat16 g_xhi[(size_t)MTOT*DD];
__device__ __nv_bfloat16 g_xlo[(size_t)MTOT*DD];
__device__ __nv_bfloat16 g_whi[(size_t)3*HH*DD];  // [w][n][k]  (B col-major layout)
__device__ __nv_bfloat16 g_wlo[(size_t)3*HH*DD];

// ---------------------------------------------------------------------------
// helpers
// ---------------------------------------------------------------------------
__device__ __forceinline__ uint32_t smem_u32(const void* p) {
    uint32_t a;
    asm("{ .reg .u64 t; cvta.to.shared.u64 t, %1; cvt.u32.u64 %0, t; }" : "=r"(a) : "l"(p));
    return a;
}
__device__ __forceinline__ void ldsm_x4(uint32_t* r, uint32_t addr) {
    asm volatile("ldmatrix.sync.aligned.m8n8.x4.shared.b16 {%0,%1,%2,%3}, [%4];"
                 : "=r"(r[0]), "=r"(r[1]), "=r"(r[2]), "=r"(r[3]) : "r"(addr));
}
__device__ __forceinline__ void mma16816(float* c, const uint32_t* a, const uint32_t* b) {
    asm volatile(
        "mma.sync.aligned.m16n8k16.row.col.f32.bf16.bf16.f32 "
        "{%0,%1,%2,%3}, {%4,%5,%6,%7}, {%8,%9}, {%0,%1,%2,%3};"
        : "+f"(c[0]), "+f"(c[1]), "+f"(c[2]), "+f"(c[3])
        : "r"(a[0]), "r"(a[1]), "r"(a[2]), "r"(a[3]), "r"(b[0]), "r"(b[1]));
}
#define CP_ASYNC16(dst, src) \
    asm volatile("cp.async.cg.shared.global [%0], [%1], 16;" :: "r"(dst), "l"(src))
#define CP_COMMIT() asm volatile("cp.async.commit_group;" ::: "memory")
#define CP_WAIT1()  asm volatile("cp.async.wait_group 1;" ::: "memory")
#define CP_WAIT0()  asm volatile("cp.async.wait_group 0;" ::: "memory")

// ---------------------------------------------------------------------------
// Split-conversion kernels
// ---------------------------------------------------------------------------
__global__ void convert_x(const float* __restrict__ x) {
    size_t i = (size_t)blockIdx.x * blockDim.x + threadIdx.x;  // float4 index
    const float4 v = ((const float4*)x)[i];
    float a[4] = {v.x, v.y, v.z, v.w};
#pragma unroll
    for (int j = 0; j < 4; j++) {
        __nv_bfloat16 hi = __float2bfloat16(a[j]);
        __nv_bfloat16 lo = __float2bfloat16(a[j] - __bfloat162float(hi));
        g_xhi[i * 4 + j] = hi;
        g_xlo[i * 4 + j] = lo;
    }
}
__global__ void convert_w(const float* __restrict__ Wq, const float* __restrict__ Wk,
                          const float* __restrict__ Wv) {
    int idx = blockIdx.x * blockDim.x + threadIdx.x;   // [w][n][k]
    if (idx >= 3 * HH * DD) return;
    int wi = idx / (HH * DD);
    int rem = idx % (HH * DD);
    int n = rem / DD, k = rem % DD;
    const float* W = (wi == 0) ? Wq : (wi == 1) ? Wk : Wv;
    float val = W[(size_t)k * HH + n];
    __nv_bfloat16 hi = __float2bfloat16(val);
    __nv_bfloat16 lo = __float2bfloat16(val - __bfloat162float(hi));
    g_whi[idx] = hi;
    g_wlo[idx] = lo;
}

// ---------------------------------------------------------------------------
// QKV projection via warp-level bf16 split MMA (mma.sync m16n8k16).
// CTA = 128x128 tile of C for one of {q,k,v}. 8 warps: 4 (M) x 2 (N).
// K loop BK=32, double-buffered cp.async. 3-pass split accumulation.
// ---------------------------------------------------------------------------
#define BK 32
#define ROWB 80                 // padded smem row stride in bytes (32 bf16 + pad)
#define BUFB (128 * ROWB)       // 10240 B per operand buffer
#define QKV_SMEM (2 * 4 * BUFB) // 2 stages x {Ahi,Alo,Bhi,Blo} = 81920 B

__global__ __launch_bounds__(256, 1)
void qkv_mma(const float* __restrict__ bq, const float* __restrict__ bk,
             const float* __restrict__ bv)
{
    extern __shared__ char smc[];
    const int tid  = threadIdx.x;
    const int lane = tid & 31;
    const int w    = tid >> 5;
    const int wm   = w & 3;       // M warp coord (4)
    const int wn   = w >> 2;      // N warp coord (2)
    const int which = blockIdx.y;
    const int m0 = blockIdx.x * 128;

    const __nv_bfloat16* srcA_hi = g_xhi + (size_t)m0 * DD;
    const __nv_bfloat16* srcA_lo = g_xlo + (size_t)m0 * DD;
    const __nv_bfloat16* srcB_hi = g_whi + (size_t)which * HH * DD;
    const __nv_bfloat16* srcB_lo = g_wlo + (size_t)which * HH * DD;
    const float* bias = (which == 0) ? bq : (which == 1) ? bk : bv;

    const uint32_t smem_base = smem_u32(smc);

    float acc[2][8][4];
#pragma unroll
    for (int mi = 0; mi < 2; mi++)
#pragma unroll
        for (int nt = 0; nt < 8; nt++)
#pragma unroll
            for (int e = 0; e < 4; e++) acc[mi][nt][e] = 0.f;

    // per-thread load geometry: chunk c = tid + it*256 -> row c>>2, part c&3
    const int ldrow0 = tid >> 2;          // rows for it=0
    const int ldrow1 = (tid + 256) >> 2;  // rows for it=1
    const int ldpart = tid & 3;

    auto load_stage = [&](int stage, int k0) {
        const __nv_bfloat16* srcs[4] = {srcA_hi, srcA_lo, srcB_hi, srcB_lo};
#pragma unroll
        for (int b = 0; b < 4; b++) {
            uint32_t dbase = smem_base + (uint32_t)(stage * 4 + b) * BUFB;
            CP_ASYNC16(dbase + ldrow0 * ROWB + ldpart * 16,
                       srcs[b] + (size_t)ldrow0 * DD + k0 + ldpart * 8);
            CP_ASYNC16(dbase + ldrow1 * ROWB + ldpart * 16,
                       srcs[b] + (size_t)ldrow1 * DD + k0 + ldpart * 8);
        }
    };

    load_stage(0, 0);
    CP_COMMIT();

    const int NIT = DD / BK;  // 32
    for (int it = 0; it < NIT; it++) {
        if (it + 1 < NIT) {
            load_stage((it + 1) & 1, (it + 1) * BK);
            CP_COMMIT();
            CP_WAIT1();
        } else {
            CP_WAIT0();
        }
        __syncthreads();

        const uint32_t stb = smem_base + (uint32_t)((it & 1) * 4) * BUFB;
        const uint32_t pAhi = stb;
        const uint32_t pAlo = stb + BUFB;
        const uint32_t pBhi = stb + 2 * BUFB;
        const uint32_t pBlo = stb + 3 * BUFB;

#pragma unroll
        for (int ks = 0; ks < BK; ks += 16) {
            // A fragments (2 m-tiles x {hi,lo})
            uint32_t ahi[2][4], alo[2][4];
#pragma unroll
            for (int mi = 0; mi < 2; mi++) {
                int row = wm * 32 + mi * 16 + (lane & 15);
                uint32_t off = (uint32_t)row * ROWB + (uint32_t)(ks + 8 * (lane >> 4)) * 2;
                ldsm_x4(ahi[mi], pAhi + off);
                ldsm_x4(alo[mi], pAlo + off);
            }
            // B fragments: 4 x (two n8-tiles each)
#pragma unroll
            for (int nt2 = 0; nt2 < 4; nt2++) {
                int j = lane >> 3;
                int nrow = wn * 64 + nt2 * 16 + 8 * (j >> 1) + (lane & 7);
                uint32_t boff = (uint32_t)nrow * ROWB + (uint32_t)(ks + 8 * (j & 1)) * 2;
                uint32_t bh[4], bl[4];
                ldsm_x4(bh, pBhi + boff);
                ldsm_x4(bl, pBlo + boff);
#pragma unroll
                for (int mi = 0; mi < 2; mi++) {
                    mma16816(acc[mi][nt2 * 2],     ahi[mi], bh);
                    mma16816(acc[mi][nt2 * 2],     alo[mi], bh);
                    mma16816(acc[mi][nt2 * 2],     ahi[mi], bl);
                    mma16816(acc[mi][nt2 * 2 + 1], ahi[mi], bh + 2);
                    mma16816(acc[mi][nt2 * 2 + 1], alo[mi], bh + 2);
                    mma16816(acc[mi][nt2 * 2 + 1], ahi[mi], bl + 2);
                }
            }
        }
        __syncthreads();
    }

    // ---- epilogue: C fragment -> gmem (+bias) ----
    const int b  = m0 / SS;
    const int s0 = m0 % SS;
    float* qkdst = (which == 0) ? g_qt : g_kt;

#pragma unroll
    for (int mi = 0; mi < 2; mi++) {
        int mrow = wm * 32 + mi * 16 + (lane >> 2);
#pragma unroll
        for (int half = 0; half < 2; half++) {
            int m = mrow + 8 * half;
#pragma unroll
            for (int nt = 0; nt < 8; nt++) {
                int n = wn * 64 + nt * 8 + (lane & 3) * 2;
                float v0 = acc[mi][nt][half * 2 + 0] + bias[n];
                float v1 = acc[mi][nt][half * 2 + 1] + bias[n + 1];
                if (which < 2) {
                    qkdst[((size_t)b * HH + n)     * SS + s0 + m] = v0;
                    qkdst[((size_t)b * HH + n + 1) * SS + s0 + m] = v1;
                } else {
                    float2 p = make_float2(v0, v1);
                    *(float2*)&g_v[(size_t)(m0 + m) * HH + n] = p;
                }
            }
        }
    }
}

// ---------------------------------------------------------------------------
// Kernel B: flash attention, causal, fp32.  (unchanged — proven)
// ---------------------------------------------------------------------------
#define TQ 64
#define TK 64
#define SSTR 68

__global__ __launch_bounds__(256, 1)
void attn_kernel(float* __restrict__ out)
{
    const int b  = blockIdx.y;
    const int qt = (int)gridDim.x - 1 - (int)blockIdx.x;
    const int q0 = qt * TQ;

    extern __shared__ float sm[];
    float* Qt   = sm;
    float* Kt   = Qt + HH * TQ;
    float* Vs   = Kt + HH * TK;
    float* Ssm  = Vs + TK * HH;
    float* rowm = Ssm + TQ * SSTR;
    float* rowl = rowm + TQ;
    float* rowa = rowl + TQ;

    const int tid = threadIdx.x;
    const int tx = tid & 15;
    const int ty = tid >> 4;

    const float* qsrc = g_qt + (size_t)b * HH * SS;
    const float* ksrc = g_kt + (size_t)b * HH * SS;
    const float* vsrc = g_v  + (size_t)b * SS * HH;

#pragma unroll
    for (int it = 0; it < 8; it++) {
        int idx = tid + it * 256;
        int h  = idx >> 4;
        int r4 = idx & 15;
        *(float4*)&Qt[h * TQ + r4 * 4] =
            *(const float4*)&qsrc[(size_t)h * SS + q0 + r4 * 4];
    }
    if (tid < TQ) { rowm[tid] = -1e30f; rowl[tid] = 0.f; }

    float acc[4][8];
#pragma unroll
    for (int i = 0; i < 4; i++)
#pragma unroll
        for (int j = 0; j < 8; j++) acc[i][j] = 0.f;

    for (int kt = 0; kt <= qt; kt++) {
        const int k0 = kt * TK;
        __syncthreads();

#pragma unroll
        for (int it = 0; it < 8; it++) {
            int idx = tid + it * 256;
            int h  = idx >> 4;
            int r4 = idx & 15;
            *(float4*)&Kt[h * TK + r4 * 4] =
                *(const float4*)&ksrc[(size_t)h * SS + k0 + r4 * 4];
        }
#pragma unroll
        for (int it = 0; it < 8; it++) {
            int idx = tid + it * 256;
            int r  = idx >> 5;
            int c4 = idx & 31;
            *(float4*)&Vs[r * HH + c4 * 4] =
                *(const float4*)&vsrc[(size_t)(k0 + r) * HH + c4 * 4];
        }
        __syncthreads();

        float s4[4][4];
#pragma unroll
        for (int i = 0; i < 4; i++)
#pragma unroll
            for (int j = 0; j < 4; j++) s4[i][j] = 0.f;

#pragma unroll 4
        for (int h = 0; h < HH; h++) {
            float4 qv = *(const float4*)&Qt[h * TQ + ty * 4];
            float4 kv = *(const float4*)&Kt[h * TK + tx * 4];
            float qa[4] = {qv.x, qv.y, qv.z, qv.w};
            float ka[4] = {kv.x, kv.y, kv.z, kv.w};
#pragma unroll
            for (int i = 0; i < 4; i++)
#pragma unroll
                for (int j = 0; j < 4; j++)
                    s4[i][j] += qa[i] * ka[j];
        }

        const int qi0 = q0 + ty * 4;
        const int kj0 = k0 + tx * 4;
#pragma unroll
        for (int i = 0; i < 4; i++) {
            float4 sv;
            float v0 = s4[i][0] * 32.f;
            float v1 = s4[i][1] * 32.f;
            float v2 = s4[i][2] * 32.f;
            float v3 = s4[i][3] * 32.f;
            int qi = qi0 + i;
            sv.x = (kj0 + 0 > qi) ? -1e30f : v0;
            sv.y = (kj0 + 1 > qi) ? -1e30f : v1;
            sv.z = (kj0 + 2 > qi) ? -1e30f : v2;
            sv.w = (kj0 + 3 > qi) ? -1e30f : v3;
            *(float4*)&Ssm[(ty * 4 + i) * SSTR + tx * 4] = sv;
        }
        __syncthreads();

        {
            int row = tid >> 2, sub = tid & 3;
            float mold = rowm[row];
            float mx = mold;
            float* srow = &Ssm[row * SSTR + sub * 16];
#pragma unroll
            for (int c = 0; c < 16; c++) mx = fmaxf(mx, srow[c]);
            mx = fmaxf(mx, __shfl_xor_sync(0xffffffffu, mx, 1));
            mx = fmaxf(mx, __shfl_xor_sync(0xffffffffu, mx, 2));
            float lsum = 0.f;
#pragma unroll
            for (int c = 0; c < 16; c++) {
                float p = __expf(srow[c] - mx);
                srow[c] = p;
                lsum += p;
            }
            lsum += __shfl_xor_sync(0xffffffffu, lsum, 1);
            lsum += __shfl_xor_sync(0xffffffffu, lsum, 2);
            if (sub == 0) {
                rowa[row] = __expf(mold - mx);
                rowm[row] = mx;
                rowl[row] = rowl[row] * rowa[row] + lsum;
            }
        }
        __syncthreads();

        float al[4];
#pragma unroll
        for (int i = 0; i < 4; i++) al[i] = rowa[ty * 4 + i];
#pragma unroll
        for (int i = 0; i < 4; i++)
#pragma unroll
            for (int j = 0; j < 8; j++) acc[i][j] *= al[i];

#pragma unroll 2
        for (int k = 0; k < TK; k++) {
            float pr[4];
#pragma unroll
            for (int i = 0; i < 4; i++) pr[i] = Ssm[(ty * 4 + i) * SSTR + k];
            float4 v0 = *(const float4*)&Vs[k * HH + tx * 4];
            float4 v1 = *(const float4*)&Vs[k * HH + 64 + tx * 4];
            float va[8] = {v0.x, v0.y, v0.z, v0.w, v1.x, v1.y, v1.z, v1.w};
#pragma unroll
            for (int i = 0; i < 4; i++)
#pragma unroll
                for (int j = 0; j < 8; j++)
                    acc[i][j] += pr[i] * va[j];
        }
    }

    float inv[4];
#pragma unroll
    for (int i = 0; i < 4; i++) inv[i] = 1.f / rowl[ty * 4 + i];
    float* obase = out + ((size_t)b * SS + q0) * HH;
#pragma unroll
    for (int i = 0; i < 4; i++) {
        float4 o0, o1;
        o0.x = acc[i][0] * inv[i]; o0.y = acc[i][1] * inv[i];
        o0.z = acc[i][2] * inv[i]; o0.w = acc[i][3] * inv[i];
        o1.x = acc[i][4] * inv[i]; o1.y = acc[i][5] * inv[i];
        o1.z = acc[i][6] * inv[i]; o1.w = acc[i][7] * inv[i];
        *(float4*)&obase[(size_t)(ty * 4 + i) * HH + tx * 4]      = o0;
        *(float4*)&obase[(size_t)(ty * 4 + i) * HH + 64 + tx * 4] = o1;
    }
}

// ---------------------------------------------------------------------------
extern "C" void kernel_launch(void* const* d_in, const int* in_sizes, int n_in,
                              void* d_out, int out_size)
{
    const float* x  = (const float*)d_in[0];
    const float* Wq = (const float*)d_in[1];
    const float* bq = (const float*)d_in[2];
    const float* Wk = (const float*)d_in[3];
    const float* bk = (const float*)d_in[4];
    const float* Wv = (const float*)d_in[5];
    const float* bv = (const float*)d_in[6];
    float* out = (float*)d_out;

    const int attn_smem = (HH * TQ + HH * TK + TK * HH + TQ * SSTR + 3 * TQ) * sizeof(float);
    cudaFuncSetAttribute(attn_kernel, cudaFuncAttributeMaxDynamicSharedMemorySize, attn_smem);
    cudaFuncSetAttribute(qkv_mma, cudaFuncAttributeMaxDynamicSharedMemorySize, QKV_SMEM);

    convert_x<<<(MTOT * DD / 4) / 256, 256>>>(x);
    convert_w<<<(3 * HH * DD + 255) / 256, 256>>>(Wq, Wk, Wv);
    qkv_mma<<<dim3(MTOT / 128, 3), 256, QKV_SMEM>>>(bq, bk, bv);
    attn_kernel<<<dim3(SS / TQ, BB), 256, attn_smem>>>(out);
}

// round 5
// speedup vs baseline: 2.6595x; 1.9338x over previous
#include <cuda_runtime.h>
#include <cuda_bf16.h>
#include <math.h>
#include <cstdint>

// Problem constants
#define BB 8
#define SS 2048
#define DD 1024
#define HH 128
#define MTOT (BB*SS)   // 16384

// ---------------------------------------------------------------------------
// Scratch (__device__ globals; no allocation allowed)
// ---------------------------------------------------------------------------
__device__ __nv_bfloat16 g_xhi[(size_t)MTOT*DD];
__device__ __nv_bfloat16 g_xlo[(size_t)MTOT*DD];
__device__ __nv_bfloat16 g_whi[(size_t)3*HH*DD];  // [w][n][k]
__device__ __nv_bfloat16 g_wlo[(size_t)3*HH*DD];

// QKV outputs, bf16 hi/lo split:
__device__ __nv_bfloat16 g_qhi[(size_t)MTOT*HH];  // [b][s][h], pre-scaled x32
__device__ __nv_bfloat16 g_qlo[(size_t)MTOT*HH];
__device__ __nv_bfloat16 g_khi[(size_t)MTOT*HH];  // [b][s][h]
__device__ __nv_bfloat16 g_klo[(size_t)MTOT*HH];
__device__ __nv_bfloat16 g_vthi[(size_t)BB*HH*SS]; // [b][h][s] (transposed)
__device__ __nv_bfloat16 g_vtlo[(size_t)BB*HH*SS];

// ---------------------------------------------------------------------------
// helpers
// ---------------------------------------------------------------------------
__device__ __forceinline__ uint32_t smem_u32(const void* p) {
    uint32_t a;
    asm("{ .reg .u64 t; cvta.to.shared.u64 t, %1; cvt.u32.u64 %0, t; }" : "=r"(a) : "l"(p));
    return a;
}
__device__ __forceinline__ void ldsm_x4(uint32_t* r, uint32_t addr) {
    asm volatile("ldmatrix.sync.aligned.m8n8.x4.shared.b16 {%0,%1,%2,%3}, [%4];"
                 : "=r"(r[0]), "=r"(r[1]), "=r"(r[2]), "=r"(r[3]) : "r"(addr));
}
__device__ __forceinline__ void mma16816(float* c, const uint32_t* a, const uint32_t* b) {
    asm volatile(
        "mma.sync.aligned.m16n8k16.row.col.f32.bf16.bf16.f32 "
        "{%0,%1,%2,%3}, {%4,%5,%6,%7}, {%8,%9}, {%0,%1,%2,%3};"
        : "+f"(c[0]), "+f"(c[1]), "+f"(c[2]), "+f"(c[3])
        : "r"(a[0]), "r"(a[1]), "r"(a[2]), "r"(a[3]), "r"(b[0]), "r"(b[1]));
}
// pack two floats (already bf16-representable or to be rounded) into bf16x2
__device__ __forceinline__ uint32_t pack_bf16(float lo_el, float hi_el) {
    uint32_t r;
    asm("cvt.rn.bf16x2.f32 %0, %1, %2;" : "=r"(r) : "f"(hi_el), "f"(lo_el));
    return r;
}
#define CP_ASYNC16(dst, src) \
    asm volatile("cp.async.cg.shared.global [%0], [%1], 16;" :: "r"(dst), "l"(src))
#define CP_COMMIT() asm volatile("cp.async.commit_group;" ::: "memory")
#define CP_WAIT1()  asm volatile("cp.async.wait_group 1;" ::: "memory")
#define CP_WAIT0()  asm volatile("cp.async.wait_group 0;" ::: "memory")

// ---------------------------------------------------------------------------
// Split-conversion kernels
// ---------------------------------------------------------------------------
__global__ void convert_x(const float* __restrict__ x) {
    size_t i = (size_t)blockIdx.x * blockDim.x + threadIdx.x;  // float4 index
    const float4 v = ((const float4*)x)[i];
    float a[4] = {v.x, v.y, v.z, v.w};
#pragma unroll
    for (int j = 0; j < 4; j++) {
        __nv_bfloat16 hi = __float2bfloat16(a[j]);
        __nv_bfloat16 lo = __float2bfloat16(a[j] - __bfloat162float(hi));
        g_xhi[i * 4 + j] = hi;
        g_xlo[i * 4 + j] = lo;
    }
}
__global__ void convert_w(const float* __restrict__ Wq, const float* __restrict__ Wk,
                          const float* __restrict__ Wv) {
    int idx = blockIdx.x * blockDim.x + threadIdx.x;   // [w][n][k]
    if (idx >= 3 * HH * DD) return;
    int wi = idx / (HH * DD);
    int rem = idx % (HH * DD);
    int n = rem / DD, k = rem % DD;
    const float* W = (wi == 0) ? Wq : (wi == 1) ? Wk : Wv;
    float val = W[(size_t)k * HH + n];
    __nv_bfloat16 hi = __float2bfloat16(val);
    __nv_bfloat16 lo = __float2bfloat16(val - __bfloat162float(hi));
    g_whi[idx] = hi;
    g_wlo[idx] = lo;
}

// ---------------------------------------------------------------------------
// QKV projection via warp-level bf16 split MMA.  (mainloop identical to R3)
// Epilogue now emits bf16 hi/lo: Q(x32),K natural [b][s][h]; V transposed.
// ---------------------------------------------------------------------------
#define BK 32
#define ROWB 80
#define BUFB (128 * ROWB)
#define QKV_SMEM (2 * 4 * BUFB)

__global__ __launch_bounds__(256, 1)
void qkv_mma(const float* __restrict__ bq, const float* __restrict__ bk,
             const float* __restrict__ bv)
{
    extern __shared__ char smc[];
    const int tid  = threadIdx.x;
    const int lane = tid & 31;
    const int w    = tid >> 5;
    const int wm   = w & 3;
    const int wn   = w >> 2;
    const int which = blockIdx.y;
    const int m0 = blockIdx.x * 128;

    const __nv_bfloat16* srcA_hi = g_xhi + (size_t)m0 * DD;
    const __nv_bfloat16* srcA_lo = g_xlo + (size_t)m0 * DD;
    const __nv_bfloat16* srcB_hi = g_whi + (size_t)which * HH * DD;
    const __nv_bfloat16* srcB_lo = g_wlo + (size_t)which * HH * DD;
    const float* bias = (which == 0) ? bq : (which == 1) ? bk : bv;

    const uint32_t smem_base = smem_u32(smc);

    float acc[2][8][4];
#pragma unroll
    for (int mi = 0; mi < 2; mi++)
#pragma unroll
        for (int nt = 0; nt < 8; nt++)
#pragma unroll
            for (int e = 0; e < 4; e++) acc[mi][nt][e] = 0.f;

    const int ldrow0 = tid >> 2;
    const int ldrow1 = (tid + 256) >> 2;
    const int ldpart = tid & 3;

    auto load_stage = [&](int stage, int k0) {
        const __nv_bfloat16* srcs[4] = {srcA_hi, srcA_lo, srcB_hi, srcB_lo};
#pragma unroll
        for (int b = 0; b < 4; b++) {
            uint32_t dbase = smem_base + (uint32_t)(stage * 4 + b) * BUFB;
            CP_ASYNC16(dbase + ldrow0 * ROWB + ldpart * 16,
                       srcs[b] + (size_t)ldrow0 * DD + k0 + ldpart * 8);
            CP_ASYNC16(dbase + ldrow1 * ROWB + ldpart * 16,
                       srcs[b] + (size_t)ldrow1 * DD + k0 + ldpart * 8);
        }
    };

    load_stage(0, 0);
    CP_COMMIT();

    const int NIT = DD / BK;
    for (int it = 0; it < NIT; it++) {
        if (it + 1 < NIT) {
            load_stage((it + 1) & 1, (it + 1) * BK);
            CP_COMMIT();
            CP_WAIT1();
        } else {
            CP_WAIT0();
        }
        __syncthreads();

        const uint32_t stb = smem_base + (uint32_t)((it & 1) * 4) * BUFB;
        const uint32_t pAhi = stb;
        const uint32_t pAlo = stb + BUFB;
        const uint32_t pBhi = stb + 2 * BUFB;
        const uint32_t pBlo = stb + 3 * BUFB;

#pragma unroll
        for (int ks = 0; ks < BK; ks += 16) {
            uint32_t ahi[2][4], alo[2][4];
#pragma unroll
            for (int mi = 0; mi < 2; mi++) {
                int row = wm * 32 + mi * 16 + (lane & 15);
                uint32_t off = (uint32_t)row * ROWB + (uint32_t)(ks + 8 * (lane >> 4)) * 2;
                ldsm_x4(ahi[mi], pAhi + off);
                ldsm_x4(alo[mi], pAlo + off);
            }
#pragma unroll
            for (int nt2 = 0; nt2 < 4; nt2++) {
                int j = lane >> 3;
                int nrow = wn * 64 + nt2 * 16 + 8 * (j >> 1) + (lane & 7);
                uint32_t boff = (uint32_t)nrow * ROWB + (uint32_t)(ks + 8 * (j & 1)) * 2;
                uint32_t bh[4], bl[4];
                ldsm_x4(bh, pBhi + boff);
                ldsm_x4(bl, pBlo + boff);
#pragma unroll
                for (int mi = 0; mi < 2; mi++) {
                    mma16816(acc[mi][nt2 * 2],     ahi[mi], bh);
                    mma16816(acc[mi][nt2 * 2],     alo[mi], bh);
                    mma16816(acc[mi][nt2 * 2],     ahi[mi], bl);
                    mma16816(acc[mi][nt2 * 2 + 1], ahi[mi], bh + 2);
                    mma16816(acc[mi][nt2 * 2 + 1], alo[mi], bh + 2);
                    mma16816(acc[mi][nt2 * 2 + 1], ahi[mi], bl + 2);
                }
            }
        }
        __syncthreads();
    }

    // ---- epilogue: fp32 acc + bias -> bf16 hi/lo split outputs ----
    const int b  = m0 / SS;
    const int s0 = m0 % SS;

#pragma unroll
    for (int mi = 0; mi < 2; mi++) {
#pragma unroll
        for (int half = 0; half < 2; half++) {
            int m = wm * 32 + mi * 16 + (lane >> 2) + 8 * half;
#pragma unroll
            for (int nt = 0; nt < 8; nt++) {
                int n = wn * 64 + nt * 8 + (lane & 3) * 2;
                float v0 = acc[mi][nt][half * 2 + 0] + bias[n];
                float v1 = acc[mi][nt][half * 2 + 1] + bias[n + 1];
                if (which == 0) { v0 *= 32.f; v1 *= 32.f; }
                __nv_bfloat16 h0 = __float2bfloat16(v0);
                __nv_bfloat16 h1 = __float2bfloat16(v1);
                __nv_bfloat16 l0 = __float2bfloat16(v0 - __bfloat162float(h0));
                __nv_bfloat16 l1 = __float2bfloat16(v1 - __bfloat162float(h1));
                if (which < 2) {
                    __nv_bfloat16* dh = (which == 0) ? g_qhi : g_khi;
                    __nv_bfloat16* dl = (which == 0) ? g_qlo : g_klo;
                    size_t addr = ((size_t)b * SS + s0 + m) * HH + n;
                    __nv_bfloat162 ph; ph.x = h0; ph.y = h1;
                    __nv_bfloat162 pl; pl.x = l0; pl.y = l1;
                    *(__nv_bfloat162*)&dh[addr] = ph;
                    *(__nv_bfloat162*)&dl[addr] = pl;
                } else {
                    size_t addr = ((size_t)b * HH + n) * SS + s0 + m;
                    g_vthi[addr]      = h0;
                    g_vthi[addr + SS] = h1;
                    g_vtlo[addr]      = l0;
                    g_vtlo[addr + SS] = l1;
                }
            }
        }
    }
}

// ---------------------------------------------------------------------------
// Flash attention via warp MMA, bf16 hi/lo split, causal, online softmax.
// TQ=64, TK=64, 4 warps x 16 rows, register-resident P, double-buffered K/V.
// ---------------------------------------------------------------------------
#define ATQ 64
#define ATK 64
#define KROWB 272   // K/Q smem row stride bytes (256B data + 16B pad)
#define VROWB 144   // V smem row stride bytes (128B data + 16B pad)
#define QB 17408          // one Q array (64*272)
#define K_OFF (2*QB)      // 34816
#define KSTG  (2*17408)   // per K stage (hi+lo)
#define KB 17408
#define V_OFF (K_OFF + 2*KSTG)   // 104448
#define VB 18432          // one V array (128*144)
#define VSTG (2*VB)
#define ATTN_SMEM (V_OFF + 2*VSTG)   // 178176

__global__ __launch_bounds__(128, 1)
void attn_mma(float* __restrict__ out)
{
    extern __shared__ char smc[];
    const uint32_t sb = smem_u32(smc);
    const int tid  = threadIdx.x;
    const int lane = tid & 31;
    const int w    = tid >> 5;                 // 0..3
    const int b    = blockIdx.y;
    const int qt   = 31 - (int)blockIdx.x;     // heavy first
    const int q0   = qt * ATQ;

    const __nv_bfloat16* qhib = g_qhi + ((size_t)b * SS + q0) * HH;
    const __nv_bfloat16* qlob = g_qlo + ((size_t)b * SS + q0) * HH;

    // ---- issue Q tile loads (hi+lo), 64 rows x 16 16B-chunks each ----
#pragma unroll
    for (int it = 0; it < 8; it++) {
        int idx = it * 128 + tid;
        int r = idx >> 4, c = idx & 15;
        CP_ASYNC16(sb + r * KROWB + c * 16, qhib + (size_t)r * HH + c * 8);
        CP_ASYNC16(sb + QB + r * KROWB + c * 16, qlob + (size_t)r * HH + c * 8);
    }

    auto load_kv = [&](int stg, int ktile) {
        const int k0 = ktile * ATK;
        uint32_t kb = sb + K_OFF + stg * KSTG;
        const __nv_bfloat16* khb = g_khi + ((size_t)b * SS + k0) * HH;
        const __nv_bfloat16* klb = g_klo + ((size_t)b * SS + k0) * HH;
#pragma unroll
        for (int it = 0; it < 8; it++) {
            int idx = it * 128 + tid;
            int r = idx >> 4, c = idx & 15;
            CP_ASYNC16(kb + r * KROWB + c * 16, khb + (size_t)r * HH + c * 8);
            CP_ASYNC16(kb + KB + r * KROWB + c * 16, klb + (size_t)r * HH + c * 8);
        }
        uint32_t vb = sb + V_OFF + stg * VSTG;
        const __nv_bfloat16* vhb = g_vthi + (size_t)b * HH * SS + k0;
        const __nv_bfloat16* vlb = g_vtlo + (size_t)b * HH * SS + k0;
#pragma unroll
        for (int it = 0; it < 8; it++) {
            int idx = it * 128 + tid;
            int r = idx >> 3, c = idx & 7;    // 128 rows x 8 chunks
            CP_ASYNC16(vb + r * VROWB + c * 16, vhb + (size_t)r * SS + c * 8);
            CP_ASYNC16(vb + VB + r * VROWB + c * 16, vlb + (size_t)r * SS + c * 8);
        }
    };

    load_kv(0, 0);
    CP_COMMIT();   // group 0: Q + KV(stage0)

    float o[16][4];
#pragma unroll
    for (int nt = 0; nt < 16; nt++)
#pragma unroll
        for (int e = 0; e < 4; e++) o[nt][e] = 0.f;
    float m0r = -1e30f, m1r = -1e30f, l0 = 0.f, l1 = 0.f;
    uint32_t qh[8][4], ql[8][4];

    for (int kt = 0; kt <= qt; kt++) {
        if (kt < qt) {
            load_kv((kt + 1) & 1, kt + 1);
            CP_COMMIT();
            CP_WAIT1();
        } else {
            CP_WAIT0();
        }
        __syncthreads();

        if (kt == 0) {
            // load Q fragments (resident for whole CTA lifetime)
            int arow = w * 16 + (lane & 15);
            uint32_t abase = (uint32_t)arow * KROWB + (uint32_t)(8 * (lane >> 4)) * 2;
#pragma unroll
            for (int ks = 0; ks < 8; ks++) {
                ldsm_x4(qh[ks], sb + abase + ks * 32);
                ldsm_x4(ql[ks], sb + QB + abase + ks * 32);
            }
        }

        const uint32_t kbase = sb + K_OFF + (kt & 1) * KSTG;
        const uint32_t vbase = sb + V_OFF + (kt & 1) * VSTG;

        // ---- S = Q K^T (pre-scaled x32), 3-pass split ----
        float S[8][4];
#pragma unroll
        for (int nt = 0; nt < 8; nt++)
#pragma unroll
            for (int e = 0; e < 4; e++) S[nt][e] = 0.f;

#pragma unroll
        for (int ks = 0; ks < 8; ks++) {
#pragma unroll
            for (int nt2 = 0; nt2 < 4; nt2++) {
                int j = lane >> 3;
                int nrow = nt2 * 16 + 8 * (j >> 1) + (lane & 7);
                uint32_t boff = (uint32_t)nrow * KROWB + (uint32_t)(ks * 16 + 8 * (j & 1)) * 2;
                uint32_t bh[4], bl[4];
                ldsm_x4(bh, kbase + boff);
                ldsm_x4(bl, kbase + KB + boff);
                mma16816(S[nt2 * 2],     qh[ks], bh);
                mma16816(S[nt2 * 2],     ql[ks], bh);
                mma16816(S[nt2 * 2],     qh[ks], bl);
                mma16816(S[nt2 * 2 + 1], qh[ks], bh + 2);
                mma16816(S[nt2 * 2 + 1], ql[ks], bh + 2);
                mma16816(S[nt2 * 2 + 1], qh[ks], bl + 2);
            }
        }

        // ---- causal mask (diagonal tile only) ----
        const int r  = lane >> 2;
        const int c2 = (lane & 3) * 2;
        if (kt == qt) {
            int lr0 = w * 16 + r;
            int lr1 = lr0 + 8;
#pragma unroll
            for (int nt = 0; nt < 8; nt++) {
                int col0 = nt * 8 + c2;
                if (col0 > lr0)     S[nt][0] = -1e30f;
                if (col0 + 1 > lr0) S[nt][1] = -1e30f;
                if (col0 > lr1)     S[nt][2] = -1e30f;
                if (col0 + 1 > lr1) S[nt][3] = -1e30f;
            }
        }

        // ---- online softmax (quad-reduced row stats) ----
        float mo0 = m0r, mo1 = m1r;
#pragma unroll
        for (int nt = 0; nt < 8; nt++) {
            m0r = fmaxf(m0r, fmaxf(S[nt][0], S[nt][1]));
            m1r = fmaxf(m1r, fmaxf(S[nt][2], S[nt][3]));
        }
        m0r = fmaxf(m0r, __shfl_xor_sync(0xffffffffu, m0r, 1));
        m0r = fmaxf(m0r, __shfl_xor_sync(0xffffffffu, m0r, 2));
        m1r = fmaxf(m1r, __shfl_xor_sync(0xffffffffu, m1r, 1));
        m1r = fmaxf(m1r, __shfl_xor_sync(0xffffffffu, m1r, 2));
        float a0 = __expf(mo0 - m0r);
        float a1 = __expf(mo1 - m1r);
#pragma unroll
        for (int nt = 0; nt < 16; nt++) {
            o[nt][0] *= a0; o[nt][1] *= a0;
            o[nt][2] *= a1; o[nt][3] *= a1;
        }
        float s0 = 0.f, s1 = 0.f;
#pragma unroll
        for (int nt = 0; nt < 8; nt++) {
            S[nt][0] = __expf(S[nt][0] - m0r);
            S[nt][1] = __expf(S[nt][1] - m0r);
            S[nt][2] = __expf(S[nt][2] - m1r);
            S[nt][3] = __expf(S[nt][3] - m1r);
            s0 += S[nt][0] + S[nt][1];
            s1 += S[nt][2] + S[nt][3];
        }
        l0 = l0 * a0 + s0;
        l1 = l1 * a1 + s1;

        // ---- pack P into A-fragments (hi/lo bf16) ----
        uint32_t ph[4][4], pl[4][4];
#pragma unroll
        for (int kp = 0; kp < 4; kp++) {
#pragma unroll
            for (int half = 0; half < 2; half++) {   // a0/a1 from ntile 2kp, a2/a3 from 2kp+1
                int nt = 2 * kp + half;
                float p0 = S[nt][0], p1 = S[nt][1];
                float p2 = S[nt][2], p3 = S[nt][3];
                float h0 = __bfloat162float(__float2bfloat16(p0));
                float h1 = __bfloat162float(__float2bfloat16(p1));
                float h2 = __bfloat162float(__float2bfloat16(p2));
                float h3 = __bfloat162float(__float2bfloat16(p3));
                ph[kp][half * 2 + 0] = pack_bf16(h0, h1);
                ph[kp][half * 2 + 1] = pack_bf16(h2, h3);
                pl[kp][half * 2 + 0] = pack_bf16(p0 - h0, p1 - h1);
                pl[kp][half * 2 + 1] = pack_bf16(p2 - h2, p3 - h3);
            }
        }
        // NOTE: a-frag ordering is {a0=(r,k0..1), a1=(r+8,k0..1), a2=(r,k8..9), a3=(r+8,k8..9)}
        // mapping above: half=0 -> a0,a1 ; half=1 -> a2,a3.  (matches C-layout identity)

        // ---- O += P V, 3-pass split ----
#pragma unroll
        for (int ks = 0; ks < 4; ks++) {
#pragma unroll
            for (int nt2 = 0; nt2 < 8; nt2++) {
                int j = lane >> 3;
                int nrow = nt2 * 16 + 8 * (j >> 1) + (lane & 7);
                uint32_t boff = (uint32_t)nrow * VROWB + (uint32_t)(ks * 16 + 8 * (j & 1)) * 2;
                uint32_t bh[4], bl[4];
                ldsm_x4(bh, vbase + boff);
                ldsm_x4(bl, vbase + VB + boff);
                mma16816(o[nt2 * 2],     ph[ks], bh);
                mma16816(o[nt2 * 2],     pl[ks], bh);
                mma16816(o[nt2 * 2],     ph[ks], bl);
                mma16816(o[nt2 * 2 + 1], ph[ks], bh + 2);
                mma16816(o[nt2 * 2 + 1], pl[ks], bh + 2);
                mma16816(o[nt2 * 2 + 1], ph[ks], bl + 2);
            }
        }
        __syncthreads();
    }

    // ---- epilogue ----
    l0 += __shfl_xor_sync(0xffffffffu, l0, 1);
    l0 += __shfl_xor_sync(0xffffffffu, l0, 2);
    l1 += __shfl_xor_sync(0xffffffffu, l1, 1);
    l1 += __shfl_xor_sync(0xffffffffu, l1, 2);
    float inv0 = 1.f / l0, inv1 = 1.f / l1;

    const int gr0 = q0 + w * 16 + (lane >> 2);
    const int gr1 = gr0 + 8;
    const int cb  = (lane & 3) * 2;
#pragma unroll
    for (int nt = 0; nt < 16; nt++) {
        int col = nt * 8 + cb;
        float2 v0 = make_float2(o[nt][0] * inv0, o[nt][1] * inv0);
        float2 v1 = make_float2(o[nt][2] * inv1, o[nt][3] * inv1);
        *(float2*)&out[((size_t)b * SS + gr0) * HH + col] = v0;
        *(float2*)&out[((size_t)b * SS + gr1) * HH + col] = v1;
    }
}

// ---------------------------------------------------------------------------
extern "C" void kernel_launch(void* const* d_in, const int* in_sizes, int n_in,
                              void* d_out, int out_size)
{
    const float* x  = (const float*)d_in[0];
    const float* Wq = (const float*)d_in[1];
    const float* bq = (const float*)d_in[2];
    const float* Wk = (const float*)d_in[3];
    const float* bk = (const float*)d_in[4];
    const float* Wv = (const float*)d_in[5];
    const float* bv = (const float*)d_in[6];
    float* out = (float*)d_out;

    cudaFuncSetAttribute(qkv_mma, cudaFuncAttributeMaxDynamicSharedMemorySize, QKV_SMEM);
    cudaFuncSetAttribute(attn_mma, cudaFuncAttributeMaxDynamicSharedMemorySize, ATTN_SMEM);

    convert_x<<<(MTOT * DD / 4) / 256, 256>>>(x);
    convert_w<<<(3 * HH * DD + 255) / 256, 256>>>(Wq, Wk, Wv);
    qkv_mma<<<dim3(MTOT / 128, 3), 256, QKV_SMEM>>>(bq, bk, bv);
    attn_mma<<<dim3(SS / ATQ, BB), 128, ATTN_SMEM>>>(out);
}